// round 17
// baseline (speedup 1.0000x reference)
#include <cuda_runtime.h>

#define N_PTS  262144
#define NLVL   16
#define TBL_T  (1u << 19)
#define TMASK  (TBL_T - 1u)
#define P1     2654435761u
#define P2     805459861u

typedef unsigned long long ull;

// floor(16 * 128^(l/15)) for l = 0..15
__constant__ float c_res[NLVL] = {
    16.f, 22.f, 30.f, 42.f, 58.f, 80.f, 111.f, 153.f,
    212.f, 294.f, 406.f, 561.f, 776.f, 1072.f, 1482.f, 2048.f
};

// All MLP weights in constant memory, 16B-aligned (LDC.128-able).
__constant__ __align__(16) float c_w0   [64 * 32];
__constant__ __align__(16) float c_wout [16 * 64];
__constant__ __align__(16) float c_rw0  [64 * 32];
__constant__ __align__(16) float c_rw1  [64 * 64];
__constant__ __align__(16) float c_rwout[3  * 64];

// ---- packed f32x2 helpers (FFMA2 via PTX) ----
__device__ __forceinline__ ull pack2(float lo, float hi) {
    ull r; asm("mov.b64 %0, {%1, %2};" : "=l"(r) : "f"(lo), "f"(hi)); return r;
}
__device__ __forceinline__ void unpack2(ull v, float& lo, float& hi) {
    asm("mov.b64 {%0, %1}, %2;" : "=f"(lo), "=f"(hi) : "l"(v));
}
__device__ __forceinline__ ull fma2(ull a, ull b, ull c) {
    ull d; asm("fma.rn.f32x2 %0, %1, %2, %3;" : "=l"(d) : "l"(a), "l"(b), "l"(c));
    return d;
}
__device__ __forceinline__ float hsum2(ull a, ull b) {
    float x0, x1, y0, y1;
    unpack2(a, x0, x1); unpack2(b, y0, y1);
    return (x0 + x1) + (y0 + y1);
}

// Half-width (32-input) dot: 16 packed pairs from `in`, weights at `wrow`.
__device__ __forceinline__ float dot32(const float* wrow, const ull* in) {
    const ulonglong2* w = (const ulonglong2*)wrow;
    ull a0 = 0ull, a1 = 0ull;
    #pragma unroll
    for (int q = 0; q < 8; ++q) {
        const ulonglong2 wp = w[q];
        a0 = fma2(wp.x, in[2 * q + 0], a0);
        a1 = fma2(wp.y, in[2 * q + 1], a1);
    }
    return hsum2(a0, a1);
}

// Two threads per point: tid&1 selects the half. Each thread hashes 8 levels,
// computes 32 of each hidden layer's 64 rows, and 64-wide dots are done as
// own-half partial + shfl_xor add (identical in both lanes).
__global__ __launch_bounds__(128, 5)
void ngp_fused(const float* __restrict__ x,
               const float* __restrict__ dvec,
               const float2* __restrict__ table,
               float* __restrict__ out)           // [N sigmas][N*3 rgbs]
{
    const int tid  = threadIdx.x;
    const int half = tid & 1;
    const int i    = blockIdx.x * 64 + (tid >> 1);   // grid exact: 4096*64 = N_PTS

    // ---------------- hash encoding: 8 levels per thread ----------------
    const float px = x[3 * i + 0] + 0.5f;
    const float py = x[3 * i + 1] + 0.5f;
    const float pz = x[3 * i + 2] + 0.5f;

    ull own[8];

    #pragma unroll 1
    for (int l = 0; l < 8; ++l) {
        const int lv = (half << 3) + l;
        const float r  = c_res[lv];
        const float fx = px * r, fy = py * r, fz = pz * r;
        const float ix = floorf(fx), iy = floorf(fy), iz = floorf(fz);
        const float tx = fx - ix, ty = fy - iy, tz = fz - iz;

        const unsigned xi = (unsigned)ix, yi = (unsigned)iy, zi = (unsigned)iz;
        const unsigned a0 = xi,            a1 = xi + 1u;
        const unsigned b0 = yi * P1,       b1 = (yi + 1u) * P1;
        const unsigned c0 = zi * P2,       c1 = (zi + 1u) * P2;

        const float2* tab = table + (size_t)lv * TBL_T;

        const float2 f000 = __ldg(tab + ((a0 ^ b0 ^ c0) & TMASK));
        const float2 f001 = __ldg(tab + ((a0 ^ b0 ^ c1) & TMASK));
        const float2 f010 = __ldg(tab + ((a0 ^ b1 ^ c0) & TMASK));
        const float2 f011 = __ldg(tab + ((a0 ^ b1 ^ c1) & TMASK));
        const float2 f100 = __ldg(tab + ((a1 ^ b0 ^ c0) & TMASK));
        const float2 f101 = __ldg(tab + ((a1 ^ b0 ^ c1) & TMASK));
        const float2 f110 = __ldg(tab + ((a1 ^ b1 ^ c0) & TMASK));
        const float2 f111 = __ldg(tab + ((a1 ^ b1 ^ c1) & TMASK));

        const float ux = 1.f - tx, uy = 1.f - ty, uz = 1.f - tz;
        const float w000 = ux * uy * uz, w001 = ux * uy * tz;
        const float w010 = ux * ty * uz, w011 = ux * ty * tz;
        const float w100 = tx * uy * uz, w101 = tx * uy * tz;
        const float w110 = tx * ty * uz, w111 = tx * ty * tz;

        float e0 = w000 * f000.x + w001 * f001.x;
        float e1 = w000 * f000.y + w001 * f001.y;
        e0 += w010 * f010.x + w011 * f011.x;
        e1 += w010 * f010.y + w011 * f011.y;
        e0 += w100 * f100.x + w101 * f101.x;
        e1 += w100 * f100.y + w101 * f101.y;
        e0 += w110 * f110.x + w111 * f111.x;
        e1 += w110 * f110.y + w111 * f111.y;

        own[l] = pack2(e0, e1);
    }

    // Pair exchange -> full emb in both threads (compile-time indices + SEL).
    ull emb2[16];
    #pragma unroll
    for (int k = 0; k < 8; ++k) {
        const ull other = __shfl_xor_sync(0xFFFFFFFFu, own[k], 1);
        emb2[k]     = half ? other  : own[k];
        emb2[8 + k] = half ? own[k] : other;
    }

    // ---------- xyz layer1: own 32 rows of 64, full-width input ----------
    ull act2[16];       // own 32 activations as 16 pairs
    #pragma unroll 4
    for (int jj = 0; jj < 32; jj += 2) {
        const int j = 32 * half + jj;
        const float s0 = fmaxf(dot32(c_w0 + (j + 0) * 32, emb2), 0.f);
        const float s1 = fmaxf(dot32(c_w0 + (j + 1) * 32, emb2), 0.f);
        act2[jj >> 1] = pack2(s0, s1);
    }

    // ---------- xyz out: 16 outputs, partial over own half + shfl-add ----
    float h[16];
    #pragma unroll
    for (int k = 0; k < 16; ++k) {
        const float part = dot32(c_wout + k * 64 + 32 * half, act2);
        h[k] = part + __shfl_xor_sync(0xFFFFFFFFu, part, 1);
    }

    if (half == 0) out[i] = expf(h[0]);   // sigma

    // ---------------- SH encoding (duplicated in both lanes) -------------
    const float dx0 = dvec[3 * i + 0];
    const float dy0 = dvec[3 * i + 1];
    const float dz0 = dvec[3 * i + 2];
    const float inv = rsqrtf(dx0 * dx0 + dy0 * dy0 + dz0 * dz0);
    const float X = dx0 * inv, Y = dy0 * inv, Z = dz0 * inv;
    const float xx = X * X, yy = Y * Y, zz = Z * Z;

    float f[16];
    f[0]  = 0.28209479177387814f;
    f[1]  = -0.4886025119029199f * Y;
    f[2]  =  0.4886025119029199f * Z;
    f[3]  = -0.4886025119029199f * X;
    f[4]  =  1.0925484305920792f * (X * Y);
    f[5]  = -1.0925484305920792f * (Y * Z);
    f[6]  =  0.31539156525252005f * (3.0f * zz - 1.0f);
    f[7]  = -1.0925484305920792f * (X * Z);
    f[8]  =  0.5462742152960396f * (xx - yy);
    f[9]  = -0.5900435899266435f * Y * (3.0f * xx - yy);
    f[10] =  2.890611442640554f  * (X * Y) * Z;
    f[11] = -0.4570457994644658f * Y * (4.0f * zz - xx - yy);
    f[12] =  0.3731763325901154f * Z * (2.0f * zz - 3.0f * xx - 3.0f * yy);
    f[13] = -0.4570457994644658f * X * (4.0f * zz - xx - yy);
    f[14] =  1.445305721320277f  * Z * (xx - yy);
    f[15] = -0.5900435899266435f * X * (xx - 3.0f * yy);

    ull f2[16];     // [sh(16) | h(16)] as 16 pairs, full in both lanes
    #pragma unroll
    for (int k = 0; k < 8; ++k) f2[k]     = pack2(f[2 * k], f[2 * k + 1]);
    #pragma unroll
    for (int k = 0; k < 8; ++k) f2[8 + k] = pack2(h[2 * k], h[2 * k + 1]);

    // ---------- rgb layer1: own 32 rows of 64, full-width input ----------
    ull act1[16];
    #pragma unroll 4
    for (int jj = 0; jj < 32; jj += 2) {
        const int j = 32 * half + jj;
        const float s0 = fmaxf(dot32(c_rw0 + (j + 0) * 32, f2), 0.f);
        const float s1 = fmaxf(dot32(c_rw0 + (j + 1) * 32, f2), 0.f);
        act1[jj >> 1] = pack2(s0, s1);
    }

    // ---- rgb layer2 (64->64, partial + shfl-add, relu) fused with 64->3 ----
    const ull* wo0 = (const ull*)(c_rwout + 0 * 64);
    const ull* wo1 = (const ull*)(c_rwout + 1 * 64);
    const ull* wo2 = (const ull*)(c_rwout + 2 * 64);
    ull racc0 = 0ull, racc1 = 0ull, racc2 = 0ull;

    #pragma unroll 4
    for (int k = 0; k < 64; k += 2) {
        const float p0 = dot32(c_rw1 + (k + 0) * 64 + 32 * half, act1);
        const float p1 = dot32(c_rw1 + (k + 1) * 64 + 32 * half, act1);
        const float t0 = fmaxf(p0 + __shfl_xor_sync(0xFFFFFFFFu, p0, 1), 0.f);
        const float t1 = fmaxf(p1 + __shfl_xor_sync(0xFFFFFFFFu, p1, 1), 0.f);
        const ull tt = pack2(t0, t1);
        racc0 = fma2(wo0[k >> 1], tt, racc0);
        racc1 = fma2(wo1[k >> 1], tt, racc1);
        racc2 = fma2(wo2[k >> 1], tt, racc2);
    }

    if (half == 1) {
        float u0, v0, u1, v1, u2, v2;
        unpack2(racc0, u0, v0);
        unpack2(racc1, u1, v1);
        unpack2(racc2, u2, v2);
        out[N_PTS + 3 * i + 0] = 1.0f / (1.0f + expf(-(u0 + v0)));
        out[N_PTS + 3 * i + 1] = 1.0f / (1.0f + expf(-(u1 + v1)));
        out[N_PTS + 3 * i + 2] = 1.0f / (1.0f + expf(-(u2 + v2)));
    }
}

extern "C" void kernel_launch(void* const* d_in, const int* in_sizes, int n_in,
                              void* d_out, int out_size)
{
    const float*  x     = (const float*)d_in[0];
    const float*  d     = (const float*)d_in[1];
    const float2* table = (const float2*)d_in[2];

    // Stage weights into constant memory (D2D memcpy nodes; graph-capturable).
    cudaMemcpyToSymbolAsync(c_w0,    d_in[3], 64 * 32 * sizeof(float), 0,
                            cudaMemcpyDeviceToDevice, 0);
    cudaMemcpyToSymbolAsync(c_wout,  d_in[4], 16 * 64 * sizeof(float), 0,
                            cudaMemcpyDeviceToDevice, 0);
    cudaMemcpyToSymbolAsync(c_rw0,   d_in[5], 64 * 32 * sizeof(float), 0,
                            cudaMemcpyDeviceToDevice, 0);
    cudaMemcpyToSymbolAsync(c_rw1,   d_in[6], 64 * 64 * sizeof(float), 0,
                            cudaMemcpyDeviceToDevice, 0);
    cudaMemcpyToSymbolAsync(c_rwout, d_in[7], 3  * 64 * sizeof(float), 0,
                            cudaMemcpyDeviceToDevice, 0);

    float* out = (float*)d_out;
    ngp_fused<<<N_PTS / 64, 128>>>(x, d, table, out);
}